// round 11
// baseline (speedup 1.0000x reference)
#include <cuda_runtime.h>
#include <cuda_fp16.h>
#include <stdint.h>

#define SEQ     2048
#define DMODEL  1024
#define NHEAD   16
#define DH      64
#define BR      128        // q rows per CTA (32 per warp)
#define BC      64         // kv rows per tile
#define NT      128
#define STRB    144        // fp16 smem row stride bytes (72 fp16)

// smem byte offsets
#define SM_QHI  0          // 128 x STRB        = 18432
#define SM_KHI  18432      //  64 x STRB        =  9216
#define SM_VHI  27648      //  64 x STRB        =  9216
#define SM_F0   36864      // fp32 stage 0: K 16384 + V 16384
#define SM_F1   69632      // fp32 stage 1
#define SM_TOTAL 102400
#define FSTAGE  32768
#define FV_OFF  16384

#define C1  0.18033688f     // 0.125 * log2(e)
#define C0  11.541560f      // 8 * log2(e)

__device__ __forceinline__ uint32_t smem_u32(const void* p) {
    uint32_t a;
    asm("{ .reg .u64 t; cvta.to.shared.u64 t, %1; cvt.u32.u64 %0, t; }" : "=r"(a) : "l"(p));
    return a;
}
__device__ __forceinline__ void ldsm4(uint32_t* r, uint32_t addr) {
    asm volatile("ldmatrix.sync.aligned.m8n8.x4.shared.b16 {%0,%1,%2,%3}, [%4];"
                 : "=r"(r[0]), "=r"(r[1]), "=r"(r[2]), "=r"(r[3]) : "r"(addr));
}
__device__ __forceinline__ void ldsm4t(uint32_t* r, uint32_t addr) {
    asm volatile("ldmatrix.sync.aligned.m8n8.x4.trans.shared.b16 {%0,%1,%2,%3}, [%4];"
                 : "=r"(r[0]), "=r"(r[1]), "=r"(r[2]), "=r"(r[3]) : "r"(addr));
}
__device__ __forceinline__ void mma16816(float* d, const uint32_t* a, const uint32_t* b) {
    asm volatile("mma.sync.aligned.m16n8k16.row.col.f32.f16.f16.f32 "
                 "{%0,%1,%2,%3}, {%4,%5,%6,%7}, {%8,%9}, {%0,%1,%2,%3};"
                 : "+f"(d[0]), "+f"(d[1]), "+f"(d[2]), "+f"(d[3])
                 : "r"(a[0]), "r"(a[1]), "r"(a[2]), "r"(a[3]), "r"(b[0]), "r"(b[1]));
}
__device__ __forceinline__ uint32_t pack2h(float x0, float x1) {
    uint32_t d;
    asm("cvt.rn.f16x2.f32 %0, %1, %2;" : "=r"(d) : "f"(x1), "f"(x0));
    return d;
}
__device__ __forceinline__ float ex2(float x) {
    float y;
    asm("ex2.approx.f32 %0, %1;" : "=f"(y) : "f"(x));
    return y;
}
__device__ __forceinline__ void cpasync16(uint32_t dst, const void* src) {
    asm volatile("cp.async.cg.shared.global [%0], [%1], 16;" :: "r"(dst), "l"(src) : "memory");
}
#define CP_COMMIT() asm volatile("cp.async.commit_group;" ::: "memory")
#define CP_WAIT0()  asm volatile("cp.async.wait_group 0;" ::: "memory")

// direct LDG loader (used only for Q)
__device__ __forceinline__ void load_q_hi(const float* __restrict__ g, char* sm_, int tid) {
#pragma unroll
    for (int it = 0; it < 16; ++it) {
        int i  = tid + it * NT;
        int r  = i >> 4;
        int c4 = (i & 15) << 2;
        float4 v = *(const float4*)(g + (size_t)r * DMODEL + c4);
        int off = r * STRB + c4 * 2;
        *(uint2*)(sm_ + SM_QHI + off) = make_uint2(pack2h(v.x, v.y), pack2h(v.z, v.w));
    }
}

// issue cp.async group: next tile's K+V fp32 -> staging buffer
__device__ __forceinline__ void issue_kv(const float* __restrict__ kg,
                                         const float* __restrict__ vg,
                                         uint32_t fbase, int tid) {
#pragma unroll
    for (int it = 0; it < 8; ++it) {
        int i  = tid + it * NT;
        int r  = i >> 4;
        int c4 = (i & 15) << 2;
        uint32_t doff = (uint32_t)(r * 64 + c4) * 4;
        cpasync16(fbase + doff,          kg + (size_t)r * DMODEL + c4);
        cpasync16(fbase + FV_OFF + doff, vg + (size_t)r * DMODEL + c4);
    }
}

// convert fp32 staging -> fp16 tiles (thread-private mapping, LDS not LDG)
__device__ __forceinline__ void convert_kv(char* sm_, int f_off, int tid) {
#pragma unroll
    for (int it = 0; it < 8; ++it) {
        int i  = tid + it * NT;
        int r  = i >> 4;
        int c4 = (i & 15) << 2;
        int soff = (r * 64 + c4) * 4;
        int doff = r * STRB + c4 * 2;
        float4 kv = *(const float4*)(sm_ + f_off + soff);
        *(uint2*)(sm_ + SM_KHI + doff) = make_uint2(pack2h(kv.x, kv.y), pack2h(kv.z, kv.w));
        float4 vv = *(const float4*)(sm_ + f_off + FV_OFF + soff);
        *(uint2*)(sm_ + SM_VHI + doff) = make_uint2(pack2h(vv.x, vv.y), pack2h(vv.z, vv.w));
    }
}

// epilogue: P = 2^(S*C1 + d*mh2 - C0) in fp32 (MUFU), pack fp16 pairs
#define EPILOGUE(sa, ph, trowA, lA, lB, DOMASK)                                        \
    {                                                                                  \
        const float dA = (float)(s0 + cb - (trowA));                                   \
        const float dB = dA - 8.0f;                                                    \
        _Pragma("unroll")                                                              \
        for (int j = 0; j < 8; ++j) {                                                  \
            const float fj = (float)(8 * j);                                           \
            const float eA = fmaf(dA + fj, mh2, -C0);                                  \
            const float eB = fmaf(dB + fj, mh2, -C0);                                  \
            float p00 = ex2(fmaf(sa[j][0], C1, eA));                                   \
            float p01 = ex2(fmaf(sa[j][1], C1, eA + mh2));                             \
            float p10 = ex2(fmaf(sa[j][2], C1, eB));                                   \
            float p11 = ex2(fmaf(sa[j][3], C1, eB + mh2));                             \
            if (DOMASK) {                                                              \
                const int sc = s0 + 8 * j + cb;                                        \
                if (sc     > (trowA))     p00 = 0.0f;                                  \
                if (sc + 1 > (trowA))     p01 = 0.0f;                                  \
                if (sc     > (trowA) + 8) p10 = 0.0f;                                  \
                if (sc + 1 > (trowA) + 8) p11 = 0.0f;                                  \
            }                                                                          \
            lA += p00 + p01;                                                           \
            lB += p10 + p11;                                                           \
            ph[j][0] = pack2h(p00, p01);                                               \
            ph[j][1] = pack2h(p10, p11);                                               \
        }                                                                              \
    }

__global__ __launch_bounds__(NT, 2)
void alibi_flash_cpa_kernel(const float* __restrict__ q,
                            const float* __restrict__ k,
                            const float* __restrict__ v,
                            float* __restrict__ out)
{
    extern __shared__ char smem[];
    const uint32_t sb = smem_u32(smem);
    const int tid  = threadIdx.x;
    const int lane = tid & 31;
    const int warp = tid >> 5;
    const int bh = blockIdx.x;
    const int b  = bh >> 4;
    const int h  = bh & 15;
    const int qt = 15 - (int)blockIdx.y;     // heavy tiles first
    const int t0 = qt * BR;
    const int m0 = warp * 32;
    const float mh2 = exp2f(-0.5f * (float)(h + 1)) * 1.44269504f;

    const int a_row  = lane & 15;
    const int a_col8 = (lane >> 4) << 3;
    const int k_row  = (lane & 7) + ((lane & 16) ? 8 : 0);
    const int k_col8 = (lane & 8) ? 8 : 0;

    const int trow0 = t0 + m0 + (lane >> 2);
    const int trow1 = trow0 + 16;
    const int cb    = (lane & 3) << 1;

    const float* kg0 = k + (size_t)b * SEQ * DMODEL + h * DH;
    const float* vg0 = v + (size_t)b * SEQ * DMODEL + h * DH;

    // ---- prologue: start tile 0 copy, then load Q while it flies ----
    issue_kv(kg0, vg0, sb + SM_F0, tid);
    CP_COMMIT();
    load_q_hi(q + ((size_t)b * SEQ + t0) * DMODEL + h * DH, smem, tid);

    float oa0[8][4], oa1[8][4];
#pragma unroll
    for (int j = 0; j < 8; ++j)
#pragma unroll
        for (int e = 0; e < 4; ++e) { oa0[j][e] = 0.0f; oa1[j][e] = 0.0f; }
    float l0A = 0.0f, l0B = 0.0f, l1A = 0.0f, l1B = 0.0f;

    const int nkv = 2 * qt + 2;
    for (int st = 0; st < nkv; ++st) {
        const int f_cur = (st & 1) ? SM_F1 : SM_F0;
        const uint32_t f_nxt = (st & 1) ? SM_F0 : SM_F1;
        const bool has_next = (st + 1 < nkv);

        CP_WAIT0();            // stage[cur] data landed (this thread's portion)
        __syncthreads();       // all threads' copies visible; fp16 tiles free for reuse

        // kick off next tile's copy immediately — full tile of compute covers it
        if (has_next) {
            issue_kv(kg0 + (size_t)(st + 1) * BC * DMODEL,
                     vg0 + (size_t)(st + 1) * BC * DMODEL, sb + f_nxt, tid);
            CP_COMMIT();
        }

        // fp32 staging -> fp16 tiles (LDS + cvt + STS, no DRAM latency)
        convert_kv(smem, f_cur, tid);
        __syncthreads();       // publish fp16 K/V

        // ===== S = Qhi Khi^T  (single product, 2 row blocks) =====
        float sa0[8][4], sa1[8][4];
#pragma unroll
        for (int j = 0; j < 8; ++j)
#pragma unroll
            for (int e = 0; e < 4; ++e) { sa0[j][e] = 0.0f; sa1[j][e] = 0.0f; }

#pragma unroll
        for (int kt = 0; kt < 4; ++kt) {
            uint32_t qh0[4], qh1[4];
            const uint32_t qoff = (uint32_t)((m0 + a_row) * STRB + (kt * 16 + a_col8) * 2);
            ldsm4(qh0, sb + SM_QHI + qoff);
            ldsm4(qh1, sb + SM_QHI + qoff + 16 * STRB);
#pragma unroll
            for (int jp = 0; jp < 4; ++jp) {
                uint32_t kh[4];
                const uint32_t koff = (uint32_t)((jp * 16 + k_row) * STRB + (kt * 16 + k_col8) * 2);
                ldsm4(kh, sb + SM_KHI + koff);
                mma16816(sa0[2 * jp],     qh0, kh);
                mma16816(sa0[2 * jp + 1], qh0, kh + 2);
                mma16816(sa1[2 * jp],     qh1, kh);
                mma16816(sa1[2 * jp + 1], qh1, kh + 2);
            }
        }

        // ===== epilogue (fp32 exp) =====
        const int s0 = st * BC;
        uint32_t ph0[8][2], ph1[8][2];
        if (st < 2 * qt) {     // fully-causal tile: no masking needed
            EPILOGUE(sa0, ph0, trow0, l0A, l0B, false)
            EPILOGUE(sa1, ph1, trow1, l1A, l1B, false)
        } else {
            EPILOGUE(sa0, ph0, trow0, l0A, l0B, true)
            EPILOGUE(sa1, ph1, trow1, l1A, l1B, true)
        }

        // ===== O += Phi Vhi  (single product, 2 row blocks) =====
#pragma unroll
        for (int kt = 0; kt < 4; ++kt) {
            uint32_t a0[4] = { ph0[2*kt][0], ph0[2*kt][1], ph0[2*kt+1][0], ph0[2*kt+1][1] };
            uint32_t a1[4] = { ph1[2*kt][0], ph1[2*kt][1], ph1[2*kt+1][0], ph1[2*kt+1][1] };
#pragma unroll
            for (int jp = 0; jp < 4; ++jp) {
                uint32_t vh[4];
                const uint32_t voff = (uint32_t)((kt * 16 + a_row) * STRB + (jp * 16 + a_col8) * 2);
                ldsm4t(vh, sb + SM_VHI + voff);
                mma16816(oa0[2 * jp],     a0, vh);
                mma16816(oa0[2 * jp + 1], a0, vh + 2);
                mma16816(oa1[2 * jp],     a1, vh);
                mma16816(oa1[2 * jp + 1], a1, vh + 2);
            }
        }
    }

    // ---- normalize and store ----
    l0A += __shfl_xor_sync(0xffffffffu, l0A, 1);
    l0A += __shfl_xor_sync(0xffffffffu, l0A, 2);
    l0B += __shfl_xor_sync(0xffffffffu, l0B, 1);
    l0B += __shfl_xor_sync(0xffffffffu, l0B, 2);
    l1A += __shfl_xor_sync(0xffffffffu, l1A, 1);
    l1A += __shfl_xor_sync(0xffffffffu, l1A, 2);
    l1B += __shfl_xor_sync(0xffffffffu, l1B, 1);
    l1B += __shfl_xor_sync(0xffffffffu, l1B, 2);
    const float i0A = 1.0f / l0A, i0B = 1.0f / l0B;
    const float i1A = 1.0f / l1A, i1B = 1.0f / l1B;

    float* ob0A = out + ((size_t)b * SEQ + trow0)      * DMODEL + h * DH;
    float* ob0B = out + ((size_t)b * SEQ + trow0 + 8)  * DMODEL + h * DH;
    float* ob1A = out + ((size_t)b * SEQ + trow1)      * DMODEL + h * DH;
    float* ob1B = out + ((size_t)b * SEQ + trow1 + 8)  * DMODEL + h * DH;
#pragma unroll
    for (int j = 0; j < 8; ++j) {
        const int e = j * 8 + cb;
        *(float2*)(ob0A + e) = make_float2(oa0[j][0] * i0A, oa0[j][1] * i0A);
        *(float2*)(ob0B + e) = make_float2(oa0[j][2] * i0B, oa0[j][3] * i0B);
        *(float2*)(ob1A + e) = make_float2(oa1[j][0] * i1A, oa1[j][1] * i1A);
        *(float2*)(ob1B + e) = make_float2(oa1[j][2] * i1B, oa1[j][3] * i1B);
    }
}

extern "C" void kernel_launch(void* const* d_in, const int* in_sizes, int n_in,
                              void* d_out, int out_size)
{
    const float* q = (const float*)d_in[0];
    const float* k = (const float*)d_in[1];
    const float* v = (const float*)d_in[2];
    float* out = (float*)d_out;

    static bool attr_set = false;
    if (!attr_set) {
        cudaFuncSetAttribute(alibi_flash_cpa_kernel,
                             cudaFuncAttributeMaxDynamicSharedMemorySize, SM_TOTAL);
        attr_set = true;
    }
    dim3 grid(32 /* b*h */, 16 /* q tiles */);
    alibi_flash_cpa_kernel<<<grid, NT, SM_TOTAL>>>(q, k, v, out);
}

// round 12
// speedup vs baseline: 1.3965x; 1.3965x over previous
#include <cuda_runtime.h>
#include <cuda_fp16.h>
#include <stdint.h>
#include <math.h>

#define SEQ     2048
#define DMODEL  1024
#define NHEAD   16
#define DH      64
#define BR      128        // q rows per CTA (32 per warp)
#define BC      64         // kv rows per tile
#define NT      128
#define STRB    144        // smem row stride bytes (72 fp16)

// smem byte offsets
#define SM_QHI  0
#define SM_KHI  18432
#define SM_VHI  27648
#define SM_TOTAL 36864

#define C1  0.18033688f     // 0.125 * log2(e)
#define C0  11.541560f      // 8 * log2(e)
#define DCUT_LOG 30.0f      // ALiBi truncation: drop kv beyond distance 30/mh2

__device__ __forceinline__ uint32_t smem_u32(const void* p) {
    uint32_t a;
    asm("{ .reg .u64 t; cvta.to.shared.u64 t, %1; cvt.u32.u64 %0, t; }" : "=r"(a) : "l"(p));
    return a;
}
__device__ __forceinline__ void ldsm4(uint32_t* r, uint32_t addr) {
    asm volatile("ldmatrix.sync.aligned.m8n8.x4.shared.b16 {%0,%1,%2,%3}, [%4];"
                 : "=r"(r[0]), "=r"(r[1]), "=r"(r[2]), "=r"(r[3]) : "r"(addr));
}
__device__ __forceinline__ void ldsm4t(uint32_t* r, uint32_t addr) {
    asm volatile("ldmatrix.sync.aligned.m8n8.x4.trans.shared.b16 {%0,%1,%2,%3}, [%4];"
                 : "=r"(r[0]), "=r"(r[1]), "=r"(r[2]), "=r"(r[3]) : "r"(addr));
}
__device__ __forceinline__ void mma16816(float* d, const uint32_t* a, const uint32_t* b) {
    asm volatile("mma.sync.aligned.m16n8k16.row.col.f32.f16.f16.f32 "
                 "{%0,%1,%2,%3}, {%4,%5,%6,%7}, {%8,%9}, {%0,%1,%2,%3};"
                 : "+f"(d[0]), "+f"(d[1]), "+f"(d[2]), "+f"(d[3])
                 : "r"(a[0]), "r"(a[1]), "r"(a[2]), "r"(a[3]), "r"(b[0]), "r"(b[1]));
}
__device__ __forceinline__ uint32_t pack2h(float x0, float x1) {
    uint32_t d;
    asm("cvt.rn.f16x2.f32 %0, %1, %2;" : "=r"(d) : "f"(x1), "f"(x0));
    return d;
}
__device__ __forceinline__ float ex2(float x) {
    float y;
    asm("ex2.approx.f32 %0, %1;" : "=f"(y) : "f"(x));
    return y;
}

// load [ROWS x 64] fp32 tile -> fp16 hi-only smem tile
template<int ROWS>
__device__ __forceinline__ void load_hi(const float* __restrict__ g, char* sm_,
                                        int off_hi, int tid) {
#pragma unroll
    for (int it = 0; it < ROWS / 8; ++it) {
        int i  = tid + it * NT;
        int r  = i >> 4;
        int c4 = (i & 15) << 2;
        float4 v = *(const float4*)(g + (size_t)r * DMODEL + c4);
        int off = r * STRB + c4 * 2;
        *(uint2*)(sm_ + off_hi + off) = make_uint2(pack2h(v.x, v.y), pack2h(v.z, v.w));
    }
}

// epilogue: P = 2^(S*C1 + d*mh2 - C0) in fp32 (MUFU), pack fp16 pairs
#define EPILOGUE(sa, ph, trowA, lA, lB, DOMASK)                                        \
    {                                                                                  \
        const float dA = (float)(s0 + cb - (trowA));                                   \
        const float dB = dA - 8.0f;                                                    \
        _Pragma("unroll")                                                              \
        for (int j = 0; j < 8; ++j) {                                                  \
            const float fj = (float)(8 * j);                                           \
            const float eA = fmaf(dA + fj, mh2, -C0);                                  \
            const float eB = fmaf(dB + fj, mh2, -C0);                                  \
            float p00 = ex2(fmaf(sa[j][0], C1, eA));                                   \
            float p01 = ex2(fmaf(sa[j][1], C1, eA + mh2));                             \
            float p10 = ex2(fmaf(sa[j][2], C1, eB));                                   \
            float p11 = ex2(fmaf(sa[j][3], C1, eB + mh2));                             \
            if (DOMASK) {                                                              \
                const int sc = s0 + 8 * j + cb;                                        \
                if (sc     > (trowA))     p00 = 0.0f;                                  \
                if (sc + 1 > (trowA))     p01 = 0.0f;                                  \
                if (sc     > (trowA) + 8) p10 = 0.0f;                                  \
                if (sc + 1 > (trowA) + 8) p11 = 0.0f;                                  \
            }                                                                          \
            lA += p00 + p01;                                                           \
            lB += p10 + p11;                                                           \
            ph[j][0] = pack2h(p00, p01);                                               \
            ph[j][1] = pack2h(p10, p11);                                               \
        }                                                                              \
    }

__global__ __launch_bounds__(NT, 2)
void alibi_flash_band_kernel(const float* __restrict__ q,
                             const float* __restrict__ k,
                             const float* __restrict__ v,
                             float* __restrict__ out)
{
    extern __shared__ char smem[];
    const uint32_t sb = smem_u32(smem);
    const int tid  = threadIdx.x;
    const int lane = tid & 31;
    const int warp = tid >> 5;
    const int bh = blockIdx.x;
    const int b  = bh >> 4;
    const int h  = bh & 15;
    const int qt = 15 - (int)blockIdx.y;     // heavy tiles first
    const int t0 = qt * BR;
    const int m0 = warp * 32;
    const float mh2 = exp2f(-0.5f * (float)(h + 1)) * 1.44269504f;

    // ---- ALiBi band truncation: keep tile st iff 64*st+63 >= t0 - D_cut ----
    const float dcut = DCUT_LOG / mh2;
    int st_min = (int)ceilf(((float)(t0 - 63) - dcut) * (1.0f / 64.0f));
    if (st_min < 0) st_min = 0;

    const int a_row  = lane & 15;
    const int a_col8 = (lane >> 4) << 3;
    const int k_row  = (lane & 7) + ((lane & 16) ? 8 : 0);
    const int k_col8 = (lane & 8) ? 8 : 0;

    const int trow0 = t0 + m0 + (lane >> 2);
    const int trow1 = trow0 + 16;
    const int cb    = (lane & 3) << 1;

    // ---- load Q tile (128 rows, fp16 hi) ----
    load_hi<128>(q + ((size_t)b * SEQ + t0) * DMODEL + h * DH, smem, SM_QHI, tid);

    float oa0[8][4], oa1[8][4];
#pragma unroll
    for (int j = 0; j < 8; ++j)
#pragma unroll
        for (int e = 0; e < 4; ++e) { oa0[j][e] = 0.0f; oa1[j][e] = 0.0f; }
    float l0A = 0.0f, l0B = 0.0f, l1A = 0.0f, l1B = 0.0f;

    const int nkv = 2 * qt + 2;
    for (int st = st_min; st < nkv; ++st) {
        if (st != st_min) __syncthreads();
        load_hi<64>(k + ((size_t)b * SEQ + st * BC) * DMODEL + h * DH, smem, SM_KHI, tid);
        load_hi<64>(v + ((size_t)b * SEQ + st * BC) * DMODEL + h * DH, smem, SM_VHI, tid);
        __syncthreads();

        // ===== S = Qhi Khi^T  (single product, 2 row blocks) =====
        float sa0[8][4], sa1[8][4];
#pragma unroll
        for (int j = 0; j < 8; ++j)
#pragma unroll
            for (int e = 0; e < 4; ++e) { sa0[j][e] = 0.0f; sa1[j][e] = 0.0f; }

#pragma unroll
        for (int kt = 0; kt < 4; ++kt) {
            uint32_t qh0[4], qh1[4];
            const uint32_t qoff = (uint32_t)((m0 + a_row) * STRB + (kt * 16 + a_col8) * 2);
            ldsm4(qh0, sb + SM_QHI + qoff);
            ldsm4(qh1, sb + SM_QHI + qoff + 16 * STRB);
#pragma unroll
            for (int jp = 0; jp < 4; ++jp) {
                uint32_t kh[4];
                const uint32_t koff = (uint32_t)((jp * 16 + k_row) * STRB + (kt * 16 + k_col8) * 2);
                ldsm4(kh, sb + SM_KHI + koff);
                mma16816(sa0[2 * jp],     qh0, kh);
                mma16816(sa0[2 * jp + 1], qh0, kh + 2);
                mma16816(sa1[2 * jp],     qh1, kh);
                mma16816(sa1[2 * jp + 1], qh1, kh + 2);
            }
        }

        // ===== epilogue (fp32 exp) =====
        const int s0 = st * BC;
        uint32_t ph0[8][2], ph1[8][2];
        if (st < 2 * qt) {     // fully-causal tile: no masking needed
            EPILOGUE(sa0, ph0, trow0, l0A, l0B, false)
            EPILOGUE(sa1, ph1, trow1, l1A, l1B, false)
        } else {
            EPILOGUE(sa0, ph0, trow0, l0A, l0B, true)
            EPILOGUE(sa1, ph1, trow1, l1A, l1B, true)
        }

        // ===== O += Phi Vhi  (single product, 2 row blocks) =====
#pragma unroll
        for (int kt = 0; kt < 4; ++kt) {
            uint32_t a0[4] = { ph0[2*kt][0], ph0[2*kt][1], ph0[2*kt+1][0], ph0[2*kt+1][1] };
            uint32_t a1[4] = { ph1[2*kt][0], ph1[2*kt][1], ph1[2*kt+1][0], ph1[2*kt+1][1] };
#pragma unroll
            for (int jp = 0; jp < 4; ++jp) {
                uint32_t vh[4];
                const uint32_t voff = (uint32_t)((kt * 16 + a_row) * STRB + (jp * 16 + a_col8) * 2);
                ldsm4t(vh, sb + SM_VHI + voff);
                mma16816(oa0[2 * jp],     a0, vh);
                mma16816(oa0[2 * jp + 1], a0, vh + 2);
                mma16816(oa1[2 * jp],     a1, vh);
                mma16816(oa1[2 * jp + 1], a1, vh + 2);
            }
        }
    }

    // ---- normalize and store ----
    l0A += __shfl_xor_sync(0xffffffffu, l0A, 1);
    l0A += __shfl_xor_sync(0xffffffffu, l0A, 2);
    l0B += __shfl_xor_sync(0xffffffffu, l0B, 1);
    l0B += __shfl_xor_sync(0xffffffffu, l0B, 2);
    l1A += __shfl_xor_sync(0xffffffffu, l1A, 1);
    l1A += __shfl_xor_sync(0xffffffffu, l1A, 2);
    l1B += __shfl_xor_sync(0xffffffffu, l1B, 1);
    l1B += __shfl_xor_sync(0xffffffffu, l1B, 2);
    const float i0A = 1.0f / l0A, i0B = 1.0f / l0B;
    const float i1A = 1.0f / l1A, i1B = 1.0f / l1B;

    float* ob0A = out + ((size_t)b * SEQ + trow0)      * DMODEL + h * DH;
    float* ob0B = out + ((size_t)b * SEQ + trow0 + 8)  * DMODEL + h * DH;
    float* ob1A = out + ((size_t)b * SEQ + trow1)      * DMODEL + h * DH;
    float* ob1B = out + ((size_t)b * SEQ + trow1 + 8)  * DMODEL + h * DH;
#pragma unroll
    for (int j = 0; j < 8; ++j) {
        const int e = j * 8 + cb;
        *(float2*)(ob0A + e) = make_float2(oa0[j][0] * i0A, oa0[j][1] * i0A);
        *(float2*)(ob0B + e) = make_float2(oa0[j][2] * i0B, oa0[j][3] * i0B);
        *(float2*)(ob1A + e) = make_float2(oa1[j][0] * i1A, oa1[j][1] * i1A);
        *(float2*)(ob1B + e) = make_float2(oa1[j][2] * i1B, oa1[j][3] * i1B);
    }
}

extern "C" void kernel_launch(void* const* d_in, const int* in_sizes, int n_in,
                              void* d_out, int out_size)
{
    const float* q = (const float*)d_in[0];
    const float* k = (const float*)d_in[1];
    const float* v = (const float*)d_in[2];
    float* out = (float*)d_out;

    static bool attr_set = false;
    if (!attr_set) {
        cudaFuncSetAttribute(alibi_flash_band_kernel,
                             cudaFuncAttributeMaxDynamicSharedMemorySize, SM_TOTAL);
        attr_set = true;
    }
    dim3 grid(32 /* b*h */, 16 /* q tiles */);
    alibi_flash_band_kernel<<<grid, NT, SM_TOTAL>>>(q, k, v, out);
}